// round 15
// baseline (speedup 1.0000x reference)
#include <cuda_runtime.h>
#include <cuda_bf16.h>
#include <math.h>
#include <stdint.h>

#define NNODES 172032
#define FIN 171

// ---------------- scratch (device globals; 16B-aligned) ----------------
__device__ __align__(16) uint32_t g_Xh[(size_t)NNODES * 96];
__device__ __align__(16) uint32_t g_Xl[(size_t)NNODES * 96];
__device__ __align__(16) uint32_t g_Y1h[(size_t)NNODES * 128];
__device__ __align__(16) uint32_t g_Y1l[(size_t)NNODES * 128];
__device__ __align__(16) uint32_t g_W1h[256 * 96];
__device__ __align__(16) uint32_t g_W1l[256 * 96];
__device__ __align__(16) uint32_t g_W2h[128 * 128];
__device__ __align__(16) uint32_t g_W2l[128 * 128];

// ---------------- helpers ----------------
__device__ __forceinline__ uint32_t smem_u32(const void* p) {
    uint32_t a;
    asm("{ .reg .u64 t; cvta.to.shared.u64 t, %1; cvt.u32.u64 %0, t; }"
        : "=r"(a) : "l"(p));
    return a;
}
__device__ __forceinline__ void cpa16(uint32_t s, const void* g) {
    asm volatile("cp.async.cg.shared.global [%0], [%1], 16;"
                 :: "r"(s), "l"(g));
}
__device__ __forceinline__ int rdidx(const void* p, long long i, bool w64) {
    return w64 ? (int)((const long long*)p)[i] : ((const int*)p)[i];
}
__device__ __forceinline__ void cvt_pair(float v0, float v1,
                                         uint32_t& hi, uint32_t& lo) {
    __nv_bfloat16 h0 = __float2bfloat16(v0), h1 = __float2bfloat16(v1);
    float r0 = v0 - __bfloat162float(h0), r1 = v1 - __bfloat162float(h1);
    __nv_bfloat16 l0 = __float2bfloat16(r0), l1 = __float2bfloat16(r1);
    hi = ((uint32_t)__bfloat16_as_ushort(h1) << 16) | __bfloat16_as_ushort(h0);
    lo = ((uint32_t)__bfloat16_as_ushort(l1) << 16) | __bfloat16_as_ushort(l0);
}

#define LDSM4(r, a)                                                        \
    asm volatile("ldmatrix.sync.aligned.m8n8.x4.shared.b16 "               \
                 "{%0,%1,%2,%3}, [%4];"                                    \
                 : "=r"((r)[0]), "=r"((r)[1]), "=r"((r)[2]), "=r"((r)[3])  \
                 : "r"(a))

#define MMA16816(d, a, b0, b1)                                             \
    asm volatile("mma.sync.aligned.m16n8k16.row.col.f32.bf16.bf16.f32 "    \
                 "{%0,%1,%2,%3},{%4,%5,%6,%7},{%8,%9},{%0,%1,%2,%3};"      \
                 : "+f"((d)[0]), "+f"((d)[1]), "+f"((d)[2]), "+f"((d)[3])  \
                 : "r"((a)[0]), "r"((a)[1]), "r"((a)[2]), "r"((a)[3]),     \
                   "r"(b0), "r"(b1))

// ---------------- sizing ----------------
// tile pitch 12 u32 (48B rows; conflict-free ldmatrix), BK=16 bf16 = 8 u32
__host__ __device__ constexpr int c_NB(int L)   { return L == 1 ? 256 : 128; }
__host__ __device__ constexpr int c_AST()       { return 2 * 96 * 48; }        // A stage stride
__host__ __device__ constexpr int c_BST(int L)  { return 2 * c_NB(L) * 48; }
__host__ __device__ constexpr int c_TB()        { return 3 * c_AST(); }        // B region base
__host__ __device__ constexpr int c_tiles(int L){ return c_TB() + 3 * c_BST(L); }
__host__ __device__ constexpr int c_P(int L)    { return L == 1 ? 257 : 129; }
__host__ __device__ constexpr int c_EX(int L)   { return 96 * c_P(L) * 4; }    // extras base (after h)
__host__ __device__ constexpr int c_ep(int L)   { return c_EX(L) + 12464; }
__host__ __device__ constexpr int c_uni(int L) {
    return c_tiles(L) > c_ep(L) ? c_tiles(L) : c_ep(L);
}

// ---------------- 0) decompose weights ----------------
__global__ void prep_w_kernel(const float* __restrict__ W1,
                              const float* __restrict__ W2)
{
    int t = blockIdx.x * blockDim.x + threadIdx.x;   // 24576 threads
    if (t < 256 * 96) {
        int n = t / 96, j = t - n * 96;
        int k0 = 2 * j;
        float v0 = (k0 < FIN) ? W1[n * FIN + k0] : 0.f;
        float v1 = (k0 + 1 < FIN) ? W1[n * FIN + k0 + 1] : 0.f;
        cvt_pair(v0, v1, g_W1h[t], g_W1l[t]);
    }
    if (t < 128 * 128) {
        int n = t / 128, j = t - n * 128;
        float v0 = W2[n * 256 + 2 * j], v1 = W2[n * 256 + 2 * j + 1];
        cvt_pair(v0, v1, g_W2h[t], g_W2l[t]);
    }
}

// ---------------- 1) build x (fp32 output + bf16 hi/lo pairs) ------------
__device__ __forceinline__ float featval(
    int node, int col, const float* x_in,
    const void* doc_id, const void* click, const void* query,
    const void* docu, const void* title,
    const float* qtab, const float* dtab, const float* ttab,
    const float* postab, const float* clktab, bool w64)
{
    if (col >= FIN) return 0.f;
    int g = node / 21, r = node - g * 21;
    if (r == 0) {
        if (col < 160) return qtab[(size_t)rdidx(query, g, w64) * 160 + col];
    } else if (r <= 10) {
        int j = r - 1;
        if (col < 160) return dtab[(size_t)rdidx(docu, (long long)g * 10 + j, w64) * 160 + col];
        if (col == 160) return postab[j];
        if (col == 161) return clktab[rdidx(click, g, w64)];
    } else {
        int j = r - 11;
        if (col < 160) return ttab[(size_t)rdidx(title, (long long)g * 10 + j, w64) * 160 + col];
    }
    return x_in[(size_t)node * FIN + col];
}

__global__ void build_x_kernel(
    const float* __restrict__ x_in, const void* __restrict__ doc_id,
    const void* __restrict__ click, const void* __restrict__ query,
    const void* __restrict__ docu, const void* __restrict__ title,
    const float* __restrict__ qtab, const float* __restrict__ dtab,
    const float* __restrict__ ttab, const float* __restrict__ postab,
    const float* __restrict__ clktab, float* __restrict__ x_out)
{
    int t = blockIdx.x * blockDim.x + threadIdx.x;   // NNODES*96 threads
    int node = t / 96, j = t - node * 96;
    bool w64 = (((const int*)doc_id)[1] == 0);
    int c0 = 2 * j;
    float v0 = featval(node, c0, x_in, doc_id, click, query, docu, title,
                       qtab, dtab, ttab, postab, clktab, w64);
    float v1 = featval(node, c0 + 1, x_in, doc_id, click, query, docu, title,
                       qtab, dtab, ttab, postab, clktab, w64);
    if (c0 < FIN)     x_out[(size_t)node * FIN + c0] = v0;
    if (c0 + 1 < FIN) x_out[(size_t)node * FIN + c0 + 1] = v1;
    cvt_pair(v0, v1, g_Xh[t], g_Xl[t]);
}

__device__ __forceinline__ int get_srcs(int r, int* s) {
    if (r == 0) {
        s[0] = 0;
        for (int j = 0; j < 10; j++) s[1 + j] = 1 + j;
        return 11;
    }
    if (r <= 10) { s[0] = 0; s[1] = r; s[2] = r + 10; return 3; }
    s[0] = r - 10; s[1] = r; return 2;
}

// ---------------- fused mma GEMM (bf16x3) + GAT aggregation --------------
// Warp tile 32x64 (2 m16 x 8 n8). BM=84 used rows (4 groups), 96 padded.
// LAYER 1: 384 thr occ1 (3M x 4N warps);  LAYER 2: 192 thr occ3 (3M x 2N).
template <int LAYER>
__global__ void __launch_bounds__((LAYER == 1 ? 384 : 192), (LAYER == 1 ? 1 : 3))
fused_mma(const float* __restrict__ avs, const float* __restrict__ avd,
          const float* __restrict__ bias, const float* __restrict__ Wl,
          const float* __restrict__ bl,
          float* __restrict__ hs_out, float* __restrict__ y_out)
{
    constexpr int THREADS = (LAYER == 1) ? 384 : 192;
    constexpr int N   = (LAYER == 1) ? 256 : 128;
    constexpr int NB  = N;
    constexpr int NW  = N / 64;                     // N warp groups: 4 / 2
    constexpr int KU  = (LAYER == 1) ? 96 : 128;    // row length (u32)
    constexpr int KT  = KU / 8;                     // 12 / 16 (BK=16 bf16)
    constexpr int P   = c_P(LAYER);
    constexpr uint32_t T_B = (uint32_t)c_TB();
    constexpr uint32_t ASTG = (uint32_t)c_AST(), AHL = 96 * 48;
    constexpr uint32_t BSTG = (uint32_t)c_BST(LAYER), BHL = NB * 48;
    constexpr uint32_t EX = (uint32_t)c_EX(LAYER);
    constexpr uint32_t X_SSP = EX, X_SDP = EX + 1536, X_SSV = EX + 3072,
                       X_SDV = EX + 3456, X_AL = EX + 3840, X_SA = EX + 7536,
                       X_SD = EX + 8560, X_SB = EX + 9584, X_WL = EX + 10608,
                       X_PT = EX + 11120;

    extern __shared__ char smem[];
    const uint32_t sb = smem_u32(smem);
    const int tid = threadIdx.x, wid = tid >> 5, lane = tid & 31;
    const int laneq = lane >> 3, laner = lane & 7;
    const int mw = wid % 3, nw = wid / 3;           // M-group, N-group
    const long long row0 = (long long)blockIdx.x * 84;

    float* ssp = (float*)(smem + X_SSP);
    float* sdp = (float*)(smem + X_SDP);
    float* ssv = (float*)(smem + X_SSV);
    float* sdv = (float*)(smem + X_SDV);
    float* alp = (float*)(smem + X_AL);
    float* sA  = (float*)(smem + X_SA);
    float* sD  = (float*)(smem + X_SD);
    float* sB  = (float*)(smem + X_SB);
    float* sWl = (float*)(smem + X_WL);
    float* part = (float*)(smem + X_PT);

    // fragment addressing
    const int rowAin = laner + (laneq & 1) * 8;
    const int coffA = (laneq >> 1) * 16;            // bytes
    const int rowBin = laner + ((laneq >> 1) ? 8 : 0);
    const int coffB = (laneq & 1) * 16;             // bytes

    uint32_t aSt[3][2], bSt[3][2];
#pragma unroll
    for (int st = 0; st < 3; st++)
#pragma unroll
        for (int hl = 0; hl < 2; hl++) {
            aSt[st][hl] = sb + st * ASTG + hl * AHL
                        + (uint32_t)(mw * 32 + rowAin) * 48 + coffA;
            bSt[st][hl] = sb + T_B + st * BSTG + hl * BHL
                        + (uint32_t)(nw * 64 + rowBin) * 48 + coffB;
        }

    auto load_tile = [&](int kt, int st) {
#pragma unroll
        for (int hl = 0; hl < 2; hl++) {
            const uint32_t* asrc = (LAYER == 1) ? (hl ? g_Xl : g_Xh)
                                                : (hl ? g_Y1l : g_Y1h);
            for (int e = tid; e < 96 * 2; e += THREADS) {
                int rm = e >> 1, c = e & 1;
                long long grow = row0 + rm;
                if (grow > NNODES - 1) grow = NNODES - 1;
                cpa16(sb + st * ASTG + hl * AHL + (uint32_t)rm * 48 + c * 16,
                      asrc + grow * KU + kt * 8 + c * 4);
            }
            const uint32_t* wsrc = (LAYER == 1) ? (hl ? g_W1l : g_W1h)
                                                : (hl ? g_W2l : g_W2h);
            for (int e = tid; e < NB * 2; e += THREADS) {
                int rn = e >> 1, c = e & 1;
                cpa16(sb + T_B + st * BSTG + hl * BHL + (uint32_t)rn * 48 + c * 16,
                      wsrc + (size_t)rn * KU + kt * 8 + c * 4);
            }
        }
        asm volatile("cp.async.commit_group;");
    };

    float d[2][8][4];
#pragma unroll
    for (int m = 0; m < 2; m++)
#pragma unroll
        for (int g = 0; g < 8; g++)
#pragma unroll
            for (int i = 0; i < 4; i++) d[m][g][i] = 0.f;

    load_tile(0, 0);
    load_tile(1, 1);

    for (int kt = 0; kt < KT; ++kt) {
        const int st = kt % 3;
        if (kt < KT - 1) asm volatile("cp.async.wait_group 1;");
        else             asm volatile("cp.async.wait_group 0;");
        __syncthreads();
        if (kt + 2 < KT) load_tile(kt + 2, (kt + 2) % 3);

        uint32_t ah[2][4], al4[2][4];
#pragma unroll
        for (int m = 0; m < 2; m++) {
            LDSM4(ah[m],  aSt[st][0] + m * 768);
            LDSM4(al4[m], aSt[st][1] + m * 768);
        }
#pragma unroll
        for (int n16 = 0; n16 < 4; n16++) {
            uint32_t bh[4], bl4[4];
            LDSM4(bh,  bSt[st][0] + n16 * 768);
            LDSM4(bl4, bSt[st][1] + n16 * 768);
#pragma unroll
            for (int m = 0; m < 2; m++) {
                MMA16816(d[m][2 * n16],     ah[m],  bh[0],  bh[1]);
                MMA16816(d[m][2 * n16],     al4[m], bh[0],  bh[1]);
                MMA16816(d[m][2 * n16],     ah[m],  bl4[0], bl4[1]);
                MMA16816(d[m][2 * n16 + 1], ah[m],  bh[2],  bh[3]);
                MMA16816(d[m][2 * n16 + 1], al4[m], bh[2],  bh[3]);
                MMA16816(d[m][2 * n16 + 1], ah[m],  bl4[2], bl4[3]);
            }
        }
    }
    __syncthreads();   // tiles dead; smem -> h + extras

    // ---- fill small tables (extras region) ----
    for (int i = tid; i < N; i += THREADS) {
        sA[i] = avs[i]; sD[i] = avd[i]; sB[i] = bias[i];
    }
    if (LAYER == 2 && tid < 128) sWl[tid] = Wl[tid];
    __syncthreads();

    // ---- store D frags to h + fused s/d dots ----
    float* h = (float*)smem;
    {
        const int rq = lane >> 2;
        float sp[2][2] = {}, dp[2][2] = {};
#pragma unroll
        for (int m = 0; m < 2; m++) {
            const int rbase = mw * 32 + m * 16 + rq;
#pragma unroll
            for (int g = 0; g < 8; g++) {
                const int c = nw * 64 + (g >> 1) * 16 + (g & 1) * 8 + 2 * (lane & 3);
                const float* dd = d[m][g];
                h[rbase * P + c]     = dd[0];
                h[rbase * P + c + 1] = dd[1];
                h[(rbase + 8) * P + c]     = dd[2];
                h[(rbase + 8) * P + c + 1] = dd[3];
                sp[m][0] += dd[0] * sA[c] + dd[1] * sA[c + 1];
                dp[m][0] += dd[0] * sD[c] + dd[1] * sD[c + 1];
                sp[m][1] += dd[2] * sA[c] + dd[3] * sA[c + 1];
                dp[m][1] += dd[2] * sD[c] + dd[3] * sD[c + 1];
            }
        }
#pragma unroll
        for (int o = 1; o <= 2; o <<= 1)
#pragma unroll
            for (int m = 0; m < 2; m++)
#pragma unroll
                for (int q = 0; q < 2; q++) {
                    sp[m][q] += __shfl_xor_sync(0xffffffffu, sp[m][q], o);
                    dp[m][q] += __shfl_xor_sync(0xffffffffu, dp[m][q], o);
                }
        if ((lane & 3) == 0) {
#pragma unroll
            for (int m = 0; m < 2; m++)
#pragma unroll
                for (int q = 0; q < 2; q++) {
                    const int r = mw * 32 + m * 16 + q * 8 + rq;
                    ssp[nw * 96 + r] = sp[m][q];
                    sdp[nw * 96 + r] = dp[m][q];
                }
        }
    }
    __syncthreads();
    if (tid < 96) {
        float s = 0.f, dv = 0.f;
#pragma unroll
        for (int q = 0; q < NW; q++) { s += ssp[q * 96 + tid]; dv += sdp[q * 96 + tid]; }
        ssv[tid] = s; sdv[tid] = dv;
    }
    __syncthreads();

    // ---- softmax attention coefficients ----
    if (tid < 84) {
        const int gi = tid / 21, r = tid - gi * 21;
        int s[11];
        const int ns = get_srcs(r, s);
        const float dv = sdv[tid];
        float e[11], m = -1e30f;
        for (int k = 0; k < ns; k++) {
            float z = ssv[gi * 21 + s[k]] + dv;
            z = (z > 0.f) ? z : 0.2f * z;
            e[k] = z;
            m = fmaxf(m, z);
        }
        float sum = 0.f;
        for (int k = 0; k < ns; k++) { e[k] = expf(e[k] - m); sum += e[k]; }
        const float inv = 1.f / sum;
        for (int k = 0; k < ns; k++) alp[tid * 11 + k] = e[k] * inv;
    }
    __syncthreads();

    // ---- aggregation + outputs ----
    if (LAYER == 1) {
        const int j = tid & 127, grp = tid >> 7;   // 0..2
        const int c0 = 2 * j;
        const float b0 = sB[c0], b1 = sB[c0 + 1];
        for (int rr = grp; rr < 84; rr += 3) {
            const int gi = rr / 21, q = rr - (rr / 21) * 21;
            int s[11];
            const int ns = get_srcs(q, s);
            float o0 = b0, o1 = b1;
            for (int k = 0; k < ns; k++) {
                const float w = alp[rr * 11 + k];
                const float* hp = &h[(gi * 21 + s[k]) * P + c0];
                o0 += w * hp[0];
                o1 += w * hp[1];
            }
            o0 = fmaxf(o0, 0.f);
            o1 = fmaxf(o1, 0.f);
            uint32_t hi, lo;
            cvt_pair(o0, o1, hi, lo);
            const long long row = row0 + rr;
            g_Y1h[row * 128 + j] = hi;
            g_Y1l[row * 128 + j] = lo;
        }
    } else {
        if (tid < 128) {
            const int col = tid;
            const float bc = sB[col], wl = sWl[col];
            for (int rr = 0; rr < 84; rr++) {
                const int gi = rr / 21, q = rr - (rr / 21) * 21;
                int s[11];
                const int ns = get_srcs(q, s);
                float o = bc;
                for (int k = 0; k < ns; k++)
                    o += alp[rr * 11 + k] * h[(gi * 21 + s[k]) * P + col];
                hs_out[(row0 + rr) * 128 + col] = o;
                float p = fmaxf(o, 0.f) * wl;
#pragma unroll
                for (int of = 16; of >= 1; of >>= 1)
                    p += __shfl_xor_sync(0xffffffffu, p, of);
                if (lane == 0) part[rr * 4 + wid] = p;
            }
        }
        __syncthreads();
        if (tid < 84) {
            const float bl0 = bl[0];
            float p = part[tid * 4] + part[tid * 4 + 1]
                    + part[tid * 4 + 2] + part[tid * 4 + 3];
            y_out[row0 + tid] = 1.f / (1.f + expf(-(p + bl0)));
        }
    }
}

// ---------------- launch ----------------
extern "C" void kernel_launch(void* const* d_in, const int* in_sizes, int n_in,
                              void* d_out, int out_size)
{
    const float* x_in   = (const float*)d_in[1];
    const void*  doc_id = d_in[3];
    const void*  click  = d_in[4];
    const void*  query  = d_in[5];
    const void*  docu   = d_in[6];
    const void*  title  = d_in[7];
    const float* qtab   = (const float*)d_in[8];
    const float* dtab   = (const float*)d_in[9];
    const float* ttab   = (const float*)d_in[10];
    const float* postab = (const float*)d_in[11];
    const float* clktab = (const float*)d_in[12];
    const float* W1  = (const float*)d_in[13];
    const float* as1 = (const float*)d_in[14];
    const float* ad1 = (const float*)d_in[15];
    const float* b1  = (const float*)d_in[16];
    const float* W2  = (const float*)d_in[17];
    const float* as2 = (const float*)d_in[18];
    const float* ad2 = (const float*)d_in[19];
    const float* b2  = (const float*)d_in[20];
    const float* Wl  = (const float*)d_in[21];
    const float* bl  = (const float*)d_in[22];

    float* out    = (float*)d_out;
    float* hs_out = out;                                   // [N,128]
    float* y_out  = out + (size_t)NNODES * 128;            // [N,1]
    float* x_out  = y_out + NNODES;                        // [N,171]

    cudaFuncSetAttribute(fused_mma<1>,
                         cudaFuncAttributeMaxDynamicSharedMemorySize, c_uni(1));
    cudaFuncSetAttribute(fused_mma<2>,
                         cudaFuncAttributeMaxDynamicSharedMemorySize, c_uni(2));

    prep_w_kernel<<<96, 256>>>(W1, W2);

    build_x_kernel<<<(NNODES * 96) / 256, 256>>>(
        x_in, doc_id, click, query, docu, title,
        qtab, dtab, ttab, postab, clktab, x_out);

    fused_mma<1><<<NNODES / 84, 384, c_uni(1)>>>(
        as1, ad1, b1, nullptr, nullptr, nullptr, nullptr);

    fused_mma<2><<<NNODES / 84, 192, c_uni(2)>>>(
        as2, ad2, b2, Wl, bl, hs_out, y_out);
}

// round 16
// speedup vs baseline: 1.6513x; 1.6513x over previous
#include <cuda_runtime.h>
#include <cuda_bf16.h>
#include <math.h>
#include <stdint.h>

#define NNODES 172032
#define FIN 171

// ---------------- scratch (device globals; 16B-aligned) ----------------
// packed bf16x2 hi/lo decompositions (low 16 bits = even-k element)
__device__ __align__(16) uint32_t g_Xh[(size_t)NNODES * 96];
__device__ __align__(16) uint32_t g_Xl[(size_t)NNODES * 96];
__device__ __align__(16) uint32_t g_Y1h[(size_t)NNODES * 128];
__device__ __align__(16) uint32_t g_Y1l[(size_t)NNODES * 128];
__device__ __align__(16) uint32_t g_W1h[256 * 96];
__device__ __align__(16) uint32_t g_W1l[256 * 96];
__device__ __align__(16) uint32_t g_W2h[128 * 128];
__device__ __align__(16) uint32_t g_W2l[128 * 128];

// ---------------- helpers ----------------
__device__ __forceinline__ uint32_t smem_u32(const void* p) {
    uint32_t a;
    asm("{ .reg .u64 t; cvta.to.shared.u64 t, %1; cvt.u32.u64 %0, t; }"
        : "=r"(a) : "l"(p));
    return a;
}
__device__ __forceinline__ void cpa16(uint32_t s, const void* g) {
    asm volatile("cp.async.cg.shared.global [%0], [%1], 16;"
                 :: "r"(s), "l"(g));
}
__device__ __forceinline__ int rdidx(const void* p, long long i, bool w64) {
    return w64 ? (int)((const long long*)p)[i] : ((const int*)p)[i];
}
__device__ __forceinline__ void cvt_pair(float v0, float v1,
                                         uint32_t& hi, uint32_t& lo) {
    __nv_bfloat16 h0 = __float2bfloat16(v0), h1 = __float2bfloat16(v1);
    float r0 = v0 - __bfloat162float(h0), r1 = v1 - __bfloat162float(h1);
    __nv_bfloat16 l0 = __float2bfloat16(r0), l1 = __float2bfloat16(r1);
    hi = ((uint32_t)__bfloat16_as_ushort(h1) << 16) | __bfloat16_as_ushort(h0);
    lo = ((uint32_t)__bfloat16_as_ushort(l1) << 16) | __bfloat16_as_ushort(l0);
}

#define LDSM4(r, a)                                                        \
    asm volatile("ldmatrix.sync.aligned.m8n8.x4.shared.b16 "               \
                 "{%0,%1,%2,%3}, [%4];"                                    \
                 : "=r"((r)[0]), "=r"((r)[1]), "=r"((r)[2]), "=r"((r)[3])  \
                 : "r"(a))

#define MMA16816(d, a, b0, b1)                                             \
    asm volatile("mma.sync.aligned.m16n8k16.row.col.f32.bf16.bf16.f32 "    \
                 "{%0,%1,%2,%3},{%4,%5,%6,%7},{%8,%9},{%0,%1,%2,%3};"      \
                 : "+f"((d)[0]), "+f"((d)[1]), "+f"((d)[2]), "+f"((d)[3])  \
                 : "r"((a)[0]), "r"((a)[1]), "r"((a)[2]), "r"((a)[3]),     \
                   "r"(b0), "r"(b1))

// ---------------- smem sizing ----------------
__host__ __device__ constexpr int c_AP(int L)   { return L == 1 ? 20 : 12; }  // tile pitch (u32)
__host__ __device__ constexpr int c_NB(int L)   { return L == 1 ? 256 : 128; }
__host__ __device__ constexpr int c_TB(int L)   { return 4 * 96 * c_AP(L) * 4; } // A region size
__host__ __device__ constexpr int c_tiles(int L){ return c_TB(L) + 4 * c_NB(L) * c_AP(L) * 4; }
__host__ __device__ constexpr int c_P(int L)    { return L == 1 ? 264 : 136; }
__host__ __device__ constexpr int c_ep(int L)   { return 96 * c_P(L) * 4; }
__host__ __device__ constexpr int c_uni(int L) {
    return c_tiles(L) > c_ep(L) ? c_tiles(L) : c_ep(L);
}
__host__ __device__ constexpr int c_smem(int L) { return c_uni(L) + 10944; }

// ---------------- 0) decompose weights ----------------
__global__ void prep_w_kernel(const float* __restrict__ W1,
                              const float* __restrict__ W2)
{
    int t = blockIdx.x * blockDim.x + threadIdx.x;   // 24576 threads
    if (t < 256 * 96) {
        int n = t / 96, j = t - n * 96;
        int k0 = 2 * j;
        float v0 = (k0 < FIN) ? W1[n * FIN + k0] : 0.f;
        float v1 = (k0 + 1 < FIN) ? W1[n * FIN + k0 + 1] : 0.f;
        cvt_pair(v0, v1, g_W1h[t], g_W1l[t]);
    }
    if (t < 128 * 128) {
        int n = t / 128, j = t - n * 128;
        float v0 = W2[n * 256 + 2 * j], v1 = W2[n * 256 + 2 * j + 1];
        cvt_pair(v0, v1, g_W2h[t], g_W2l[t]);
    }
}

// ---------------- 1) build x (fp32 output + bf16 hi/lo pairs) ------------
__device__ __forceinline__ float featval(
    int node, int col, const float* x_in,
    const void* doc_id, const void* click, const void* query,
    const void* docu, const void* title,
    const float* qtab, const float* dtab, const float* ttab,
    const float* postab, const float* clktab, bool w64)
{
    if (col >= FIN) return 0.f;
    int g = node / 21, r = node - g * 21;
    if (r == 0) {
        if (col < 160) return qtab[(size_t)rdidx(query, g, w64) * 160 + col];
    } else if (r <= 10) {
        int j = r - 1;
        if (col < 160) return dtab[(size_t)rdidx(docu, (long long)g * 10 + j, w64) * 160 + col];
        if (col == 160) return postab[j];
        if (col == 161) return clktab[rdidx(click, g, w64)];
    } else {
        int j = r - 11;
        if (col < 160) return ttab[(size_t)rdidx(title, (long long)g * 10 + j, w64) * 160 + col];
    }
    return x_in[(size_t)node * FIN + col];
}

__global__ void build_x_kernel(
    const float* __restrict__ x_in, const void* __restrict__ doc_id,
    const void* __restrict__ click, const void* __restrict__ query,
    const void* __restrict__ docu, const void* __restrict__ title,
    const float* __restrict__ qtab, const float* __restrict__ dtab,
    const float* __restrict__ ttab, const float* __restrict__ postab,
    const float* __restrict__ clktab, float* __restrict__ x_out)
{
    int t = blockIdx.x * blockDim.x + threadIdx.x;   // NNODES*96 threads
    int node = t / 96, j = t - node * 96;
    bool w64 = (((const int*)doc_id)[1] == 0);
    int c0 = 2 * j;
    float v0 = featval(node, c0, x_in, doc_id, click, query, docu, title,
                       qtab, dtab, ttab, postab, clktab, w64);
    float v1 = featval(node, c0 + 1, x_in, doc_id, click, query, docu, title,
                       qtab, dtab, ttab, postab, clktab, w64);
    if (c0 < FIN)     x_out[(size_t)node * FIN + c0] = v0;
    if (c0 + 1 < FIN) x_out[(size_t)node * FIN + c0 + 1] = v1;
    cvt_pair(v0, v1, g_Xh[t], g_Xl[t]);
}

__device__ __forceinline__ int get_srcs(int r, int* s) {
    if (r == 0) {
        s[0] = 0;
        for (int j = 0; j < 10; j++) s[1 + j] = 1 + j;
        return 11;
    }
    if (r <= 10) { s[0] = 0; s[1] = r; s[2] = r + 10; return 3; }
    s[0] = r - 10; s[1] = r; return 2;
}

// ---------------- fused mma GEMM (bf16x3) + GAT aggregation --------------
// BM=84 rows (4 groups) per CTA, MP=96 padded (6 m16 tiles).
// LAYER 1: 384 thr occ1, N=256, BK=32 bf16;  LAYER 2: 192 thr occ3, N=128, BK=16 bf16.
template <int LAYER>
__global__ void __launch_bounds__((LAYER == 1 ? 384 : 192), (LAYER == 1 ? 1 : 3))
fused_mma(const float* __restrict__ avs, const float* __restrict__ avd,
          const float* __restrict__ bias, const float* __restrict__ Wl,
          const float* __restrict__ bl,
          float* __restrict__ hs_out, float* __restrict__ y_out)
{
    constexpr int THREADS = (LAYER == 1) ? 384 : 192;
    constexpr int N   = (LAYER == 1) ? 256 : 128;
    constexpr int NB  = N;
    constexpr int KU  = (LAYER == 1) ? 96 : 128;   // global row length (u32)
    constexpr int AP  = c_AP(LAYER);               // tile pitch (u32)
    constexpr int CPR = (LAYER == 1) ? 4 : 2;      // 16B copies per row
    constexpr int SST = (LAYER == 1) ? 2 : 1;      // k16 steps per tile
    constexpr int KT  = KU / (CPR * 4);            // 6 / 16
    constexpr int P   = c_P(LAYER);
    constexpr uint32_t T_A = 0, T_B = (uint32_t)c_TB(LAYER);
    constexpr uint32_t UNI = (uint32_t)c_uni(LAYER);
    constexpr uint32_t X_SSP = UNI, X_SDP = UNI + 768, X_SSV = UNI + 1536,
                       X_SDV = UNI + 1920, X_AL = UNI + 2304, X_SA = UNI + 6000,
                       X_SD = UNI + 7024, X_SB = UNI + 8048, X_WL = UNI + 9072,
                       X_PT = UNI + 9584;

    extern __shared__ char smem[];
    const uint32_t sb = smem_u32(smem);
    const int tid = threadIdx.x, wid = tid >> 5, lane = tid & 31;
    const int laneq = lane >> 3, laner = lane & 7;
    const int mt = (LAYER == 1) ? (wid % 6) : wid;
    const int nh = (LAYER == 1) ? (wid / 6) : 0;
    const long long row0 = (long long)blockIdx.x * 84;

    float* ssp = (float*)(smem + X_SSP);
    float* sdp = (float*)(smem + X_SDP);
    float* ssv = (float*)(smem + X_SSV);
    float* sdv = (float*)(smem + X_SDV);
    float* alp = (float*)(smem + X_AL);
    float* sA  = (float*)(smem + X_SA);
    float* sD  = (float*)(smem + X_SD);
    float* sB  = (float*)(smem + X_SB);
    float* sWl = (float*)(smem + X_WL);
    float* part = (float*)(smem + X_PT);

    for (int i = tid; i < N; i += THREADS) {
        sA[i] = avs[i]; sD[i] = avd[i]; sB[i] = bias[i];
    }
    if (LAYER == 2 && tid < 128) sWl[tid] = Wl[tid];

    // fragment row/col selectors
    const int rowA = mt * 16 + laner + (laneq & 1) * 8;
    const int coffA = (laneq >> 1) * 4;
    const int rowBoff = laner + ((laneq >> 1) ? 8 : 0);
    const int coffB = (laneq & 1) * 4;

    // hoisted LDSM base addresses [buf][hl]
    uint32_t aB[2][2], bB[2][2];
#pragma unroll
    for (int b2 = 0; b2 < 2; b2++)
#pragma unroll
        for (int hl = 0; hl < 2; hl++) {
            aB[b2][hl] = sb + T_A + (uint32_t)(((b2 * 2 + hl) * 96 + rowA) * AP + coffA) * 4;
            bB[b2][hl] = sb + T_B + (uint32_t)(((b2 * 2 + hl) * NB + nh * 128 + rowBoff) * AP + coffB) * 4;
        }

    auto load_tile = [&](int kt, int buf) {
#pragma unroll
        for (int hl = 0; hl < 2; hl++) {
            const uint32_t* asrc = (LAYER == 1) ? (hl ? g_Xl : g_Xh)
                                                : (hl ? g_Y1l : g_Y1h);
            for (int e = tid; e < 96 * CPR; e += THREADS) {
                int rm = e / CPR, c = e - (e / CPR) * CPR;
                long long grow = row0 + rm;
                if (grow > NNODES - 1) grow = NNODES - 1;
                cpa16(sb + T_A + (uint32_t)(((buf * 2 + hl) * 96 + rm) * AP + c * 4) * 4,
                      asrc + grow * KU + kt * (CPR * 4) + c * 4);
            }
            const uint32_t* wsrc = (LAYER == 1) ? (hl ? g_W1l : g_W1h)
                                                : (hl ? g_W2l : g_W2h);
            for (int e = tid; e < NB * CPR; e += THREADS) {
                int rn = e / CPR, c = e - (e / CPR) * CPR;
                cpa16(sb + T_B + (uint32_t)(((buf * 2 + hl) * NB + rn) * AP + c * 4) * 4,
                      wsrc + (size_t)rn * KU + kt * (CPR * 4) + c * 4);
            }
        }
        asm volatile("cp.async.commit_group;");
    };

    float d[16][4];
#pragma unroll
    for (int t = 0; t < 16; t++)
#pragma unroll
        for (int i = 0; i < 4; i++) d[t][i] = 0.f;

    load_tile(0, 0);

    for (int kt = 0; kt < KT; ++kt) {
        const int buf = kt & 1;
        asm volatile("cp.async.wait_group 0;");
        __syncthreads();
        if (kt + 1 < KT) load_tile(kt + 1, buf ^ 1);

#pragma unroll
        for (int s = 0; s < SST; s++) {
            const uint32_t j0 = s * 32;   // s*8 u32 in bytes
            uint32_t ah[4], al4[4];
            LDSM4(ah,  aB[buf][0] + j0);
            LDSM4(al4, aB[buf][1] + j0);
#pragma unroll
            for (int g = 0; g < 8; g++) {
                const uint32_t bo = (uint32_t)(g * 16 * AP * 4) + j0;
                uint32_t bh[4], bl4[4];
                LDSM4(bh,  bB[buf][0] + bo);
                LDSM4(bl4, bB[buf][1] + bo);
                // interleaved across the two independent accumulators:
                // RAW distance 2 instead of 1 on every HMMA
                MMA16816(d[2 * g],     ah,  bh[0],  bh[1]);
                MMA16816(d[2 * g + 1], ah,  bh[2],  bh[3]);
                MMA16816(d[2 * g],     al4, bh[0],  bh[1]);
                MMA16816(d[2 * g + 1], al4, bh[2],  bh[3]);
                MMA16816(d[2 * g],     ah,  bl4[0], bl4[1]);
                MMA16816(d[2 * g + 1], ah,  bl4[2], bl4[3]);
            }
        }
    }
    __syncthreads();   // all tile reads done; union -> h

    // ---- store D frags to h smem + fused s/d partials ----
    float* h = (float*)smem;
    {
        const int r0r = mt * 16 + (lane >> 2);
        float spL = 0.f, dpL = 0.f, spH = 0.f, dpH = 0.f;
#pragma unroll
        for (int t = 0; t < 16; t++) {
            const int c = nh * 128 + (t >> 1) * 16 + (t & 1) * 8 + 2 * (lane & 3);
            h[r0r * P + c]     = d[t][0];
            h[r0r * P + c + 1] = d[t][1];
            h[(r0r + 8) * P + c]     = d[t][2];
            h[(r0r + 8) * P + c + 1] = d[t][3];
            spL += d[t][0] * sA[c] + d[t][1] * sA[c + 1];
            dpL += d[t][0] * sD[c] + d[t][1] * sD[c + 1];
            spH += d[t][2] * sA[c] + d[t][3] * sA[c + 1];
            dpH += d[t][2] * sD[c] + d[t][3] * sD[c + 1];
        }
#pragma unroll
        for (int o = 1; o <= 2; o <<= 1) {
            spL += __shfl_xor_sync(0xffffffffu, spL, o);
            dpL += __shfl_xor_sync(0xffffffffu, dpL, o);
            spH += __shfl_xor_sync(0xffffffffu, spH, o);
            dpH += __shfl_xor_sync(0xffffffffu, dpH, o);
        }
        if ((lane & 3) == 0) {
            ssp[nh * 96 + r0r] = spL; sdp[nh * 96 + r0r] = dpL;
            ssp[nh * 96 + r0r + 8] = spH; sdp[nh * 96 + r0r + 8] = dpH;
        }
    }
    __syncthreads();
    if (tid < 96) {
        ssv[tid] = (LAYER == 1) ? (ssp[tid] + ssp[96 + tid]) : ssp[tid];
        sdv[tid] = (LAYER == 1) ? (sdp[tid] + sdp[96 + tid]) : sdp[tid];
    }
    __syncthreads();

    // ---- softmax attention coefficients ----
    if (tid < 84) {
        const int gi = tid / 21, r = tid - gi * 21;
        int s[11];
        const int ns = get_srcs(r, s);
        const float dv = sdv[tid];
        float e[11], m = -1e30f;
        for (int k = 0; k < ns; k++) {
            float z = ssv[gi * 21 + s[k]] + dv;
            z = (z > 0.f) ? z : 0.2f * z;
            e[k] = z;
            m = fmaxf(m, z);
        }
        float sum = 0.f;
        for (int k = 0; k < ns; k++) { e[k] = expf(e[k] - m); sum += e[k]; }
        const float inv = 1.f / sum;
        for (int k = 0; k < ns; k++) alp[tid * 11 + k] = e[k] * inv;
    }
    __syncthreads();

    // ---- aggregation + outputs ----
    if (LAYER == 1) {
        const int j = tid & 127, grp = tid >> 7;   // 0..2
        const int c0 = 2 * j;
        const float b0 = sB[c0], b1 = sB[c0 + 1];
        for (int rr = grp; rr < 84; rr += 3) {
            const int gi = rr / 21, q = rr - (rr / 21) * 21;
            int s[11];
            const int ns = get_srcs(q, s);
            float o0 = b0, o1 = b1;
            for (int k = 0; k < ns; k++) {
                const float w = alp[rr * 11 + k];
                const float* hp = &h[(gi * 21 + s[k]) * P + c0];
                o0 += w * hp[0];
                o1 += w * hp[1];
            }
            o0 = fmaxf(o0, 0.f);
            o1 = fmaxf(o1, 0.f);
            uint32_t hi, lo;
            cvt_pair(o0, o1, hi, lo);
            const long long row = row0 + rr;
            g_Y1h[row * 128 + j] = hi;
            g_Y1l[row * 128 + j] = lo;
        }
    } else {
        if (tid < 128) {
            const int col = tid;
            const float bc = sB[col], wl = sWl[col];
            for (int rr = 0; rr < 84; rr++) {
                const int gi = rr / 21, q = rr - (rr / 21) * 21;
                int s[11];
                const int ns = get_srcs(q, s);
                float o = bc;
                for (int k = 0; k < ns; k++)
                    o += alp[rr * 11 + k] * h[(gi * 21 + s[k]) * P + col];
                hs_out[(row0 + rr) * 128 + col] = o;
                float p = fmaxf(o, 0.f) * wl;
#pragma unroll
                for (int of = 16; of >= 1; of >>= 1)
                    p += __shfl_xor_sync(0xffffffffu, p, of);
                if (lane == 0) part[rr * 4 + wid] = p;
            }
        }
        __syncthreads();
        if (tid < 84) {
            const float bl0 = bl[0];
            float p = part[tid * 4] + part[tid * 4 + 1]
                    + part[tid * 4 + 2] + part[tid * 4 + 3];
            y_out[row0 + tid] = 1.f / (1.f + expf(-(p + bl0)));
        }
    }
}

// ---------------- launch ----------------
extern "C" void kernel_launch(void* const* d_in, const int* in_sizes, int n_in,
                              void* d_out, int out_size)
{
    const float* x_in   = (const float*)d_in[1];
    const void*  doc_id = d_in[3];
    const void*  click  = d_in[4];
    const void*  query  = d_in[5];
    const void*  docu   = d_in[6];
    const void*  title  = d_in[7];
    const float* qtab   = (const float*)d_in[8];
    const float* dtab   = (const float*)d_in[9];
    const float* ttab   = (const float*)d_in[10];
    const float* postab = (const float*)d_in[11];
    const float* clktab = (const float*)d_in[12];
    const float* W1  = (const float*)d_in[13];
    const float* as1 = (const float*)d_in[14];
    const float* ad1 = (const float*)d_in[15];
    const float* b1  = (const float*)d_in[16];
    const float* W2  = (const float*)d_in[17];
    const float* as2 = (const float*)d_in[18];
    const float* ad2 = (const float*)d_in[19];
    const float* b2  = (const float*)d_in[20];
    const float* Wl  = (const float*)d_in[21];
    const float* bl  = (const float*)d_in[22];

    float* out    = (float*)d_out;
    float* hs_out = out;                                   // [N,128]
    float* y_out  = out + (size_t)NNODES * 128;            // [N,1]
    float* x_out  = y_out + NNODES;                        // [N,171]

    cudaFuncSetAttribute(fused_mma<1>,
                         cudaFuncAttributeMaxDynamicSharedMemorySize, c_smem(1));
    cudaFuncSetAttribute(fused_mma<2>,
                         cudaFuncAttributeMaxDynamicSharedMemorySize, c_smem(2));

    prep_w_kernel<<<96, 256>>>(W1, W2);

    build_x_kernel<<<(NNODES * 96) / 256, 256>>>(
        x_in, doc_id, click, query, docu, title,
        qtab, dtab, ttab, postab, clktab, x_out);

    fused_mma<1><<<NNODES / 84, 384, c_smem(1)>>>(
        as1, ad1, b1, nullptr, nullptr, nullptr, nullptr);

    fused_mma<2><<<NNODES / 84, 192, c_smem(2)>>>(
        as2, ad2, b2, Wl, bl, hs_out, y_out);
}